// round 1
// baseline (speedup 1.0000x reference)
#include <cuda_runtime.h>
#include <math.h>

#define Bdim 64
#define Tdim 512
#define IDIM 512
#define Hdim 512
#define Odim 512

#define NBLK 128   // persistent grid for the scan kernel
#define RPB  16    // rows per block (Hdim/32 row-groups)
#define BPB  16    // batches per block (Bdim/4 batch-groups)

// Scratch: xin[b,t,h] (64 MB). __device__ global => no allocation.
__device__ float g_xin[(size_t)Bdim * Tdim * Hdim];

// Grid barrier state (returns to count=0 after every barrier; gen monotonic)
__device__ unsigned g_count = 0;
__device__ unsigned g_gen = 0;

__device__ __forceinline__ void gridbar() {
    __syncthreads();
    if (threadIdx.x == 0) {
        unsigned gen = *(volatile unsigned*)&g_gen;
        __threadfence();
        unsigned arr = atomicAdd(&g_count, 1u);
        if (arr == NBLK - 1) {
            *(volatile unsigned*)&g_count = 0u;
            __threadfence();
            atomicAdd(&g_gen, 1u);
        } else {
            while (*(volatile unsigned*)&g_gen == gen) { __nanosleep(64); }
        }
        __threadfence();
    }
    __syncthreads();
}

// ---------------------------------------------------------------------------
// Kernel A: g_xin[m, h] = sum_i emb[m, i] * W_in[h, i] + b_in[h]
// M = B*T = 32768, N = H = 512, K = I = 512. Tiled fp32 SGEMM (NT).
// ---------------------------------------------------------------------------
#define BM 64
#define BN 64
#define BK 16

__global__ __launch_bounds__(256) void gemm_xin(const float* __restrict__ A,
                                                const float* __restrict__ W,
                                                const float* __restrict__ bias) {
    __shared__ float Ast[BK][BM + 4];
    __shared__ float Bst[BK][BN + 4];
    const int bn = blockIdx.x;   // 0..7
    const int bm = blockIdx.y;   // 0..511
    const int tid = threadIdx.x;

    const int lr = tid >> 2;          // 0..63 : row within tile
    const int lc = (tid & 3) << 2;    // 0,4,8,12 : k offset
    const int tx = tid & 15;          // n sub-tile
    const int ty = tid >> 4;          // m sub-tile

    float acc[4][4];
#pragma unroll
    for (int i = 0; i < 4; i++)
#pragma unroll
        for (int j = 0; j < 4; j++) acc[i][j] = 0.0f;

    const float* Ab = A + (size_t)(bm * BM) * IDIM;
    const float* Wb = W + (size_t)(bn * BN) * IDIM;

    for (int kt = 0; kt < IDIM; kt += BK) {
        float4 av = *(const float4*)(Ab + (size_t)lr * IDIM + kt + lc);
        float4 wv = *(const float4*)(Wb + (size_t)lr * IDIM + kt + lc);
        Ast[lc + 0][lr] = av.x; Ast[lc + 1][lr] = av.y;
        Ast[lc + 2][lr] = av.z; Ast[lc + 3][lr] = av.w;
        Bst[lc + 0][lr] = wv.x; Bst[lc + 1][lr] = wv.y;
        Bst[lc + 2][lr] = wv.z; Bst[lc + 3][lr] = wv.w;
        __syncthreads();
#pragma unroll
        for (int kk = 0; kk < BK; kk++) {
            float4 a4 = *(const float4*)&Ast[kk][ty * 4];
            float4 b4 = *(const float4*)&Bst[kk][tx * 4];
            acc[0][0] = fmaf(a4.x, b4.x, acc[0][0]);
            acc[0][1] = fmaf(a4.x, b4.y, acc[0][1]);
            acc[0][2] = fmaf(a4.x, b4.z, acc[0][2]);
            acc[0][3] = fmaf(a4.x, b4.w, acc[0][3]);
            acc[1][0] = fmaf(a4.y, b4.x, acc[1][0]);
            acc[1][1] = fmaf(a4.y, b4.y, acc[1][1]);
            acc[1][2] = fmaf(a4.y, b4.z, acc[1][2]);
            acc[1][3] = fmaf(a4.y, b4.w, acc[1][3]);
            acc[2][0] = fmaf(a4.z, b4.x, acc[2][0]);
            acc[2][1] = fmaf(a4.z, b4.y, acc[2][1]);
            acc[2][2] = fmaf(a4.z, b4.z, acc[2][2]);
            acc[2][3] = fmaf(a4.z, b4.w, acc[2][3]);
            acc[3][0] = fmaf(a4.w, b4.x, acc[3][0]);
            acc[3][1] = fmaf(a4.w, b4.y, acc[3][1]);
            acc[3][2] = fmaf(a4.w, b4.z, acc[3][2]);
            acc[3][3] = fmaf(a4.w, b4.w, acc[3][3]);
        }
        __syncthreads();
    }

    const int n0 = bn * BN + tx * 4;
    float4 bsv = *(const float4*)&bias[n0];
#pragma unroll
    for (int i = 0; i < 4; i++) {
        int m = bm * BM + ty * 4 + i;
        float4 o;
        o.x = acc[i][0] + bsv.x;
        o.y = acc[i][1] + bsv.y;
        o.z = acc[i][2] + bsv.z;
        o.w = acc[i][3] + bsv.w;
        *(float4*)&g_xin[(size_t)m * Hdim + n0] = o;
    }
}

// ---------------------------------------------------------------------------
// Kernel B: persistent Jordan scan.
// Grid = 128 blocks = 4 batch-groups (16 batches) x 32 row-groups (16 rows).
// SMEM: W_y slice [16x512], W_out slice [16x512], activation stage [16x512].
// Warp layout: warp w -> bg2=w>>1 (4 batches), rg2=w&1 (8 rows); lanes split K.
// ---------------------------------------------------------------------------

// Per-warp register-tiled matvec partial: acc[i2*8+p] = sum over this lane's
// K strides of act[b,k]*W[r,k]; then tree shuffle-reduce so lane kc ends with
// the full dot for output index (i2 = kc>>3, p = kc&7) in acc[0].
__device__ __forceinline__ float matvec_tile(const float* __restrict__ sW,
                                             const float* __restrict__ sA,
                                             int kc, int bg2, int rg2) {
    const float* wp = sW + (rg2 * 8) * 512 + kc;
    const float* ap = sA + (bg2 * 4) * 512 + kc;
    float acc[32];
#pragma unroll
    for (int a = 0; a < 32; a++) acc[a] = 0.0f;
#pragma unroll
    for (int j = 0; j < 16; j++) {
        const int k = 32 * j;
        float yv[4], wv[8];
#pragma unroll
        for (int i2 = 0; i2 < 4; i2++) yv[i2] = ap[i2 * 512 + k];
#pragma unroll
        for (int p = 0; p < 8; p++) wv[p] = wp[p * 512 + k];
#pragma unroll
        for (int i2 = 0; i2 < 4; i2++)
#pragma unroll
            for (int p = 0; p < 8; p++)
                acc[i2 * 8 + p] = fmaf(yv[i2], wv[p], acc[i2 * 8 + p]);
    }
    // Tree reduction across lanes: lane l ends with total of original acc[l].
#pragma unroll
    for (int s = 16; s >= 1; s >>= 1) {
        const bool up = (kc & s);
#pragma unroll
        for (int a = 0; a < s; a++) {
            float send = up ? acc[a] : acc[a + s];
            float recv = __shfl_xor_sync(0xffffffffu, send, s);
            acc[a] = (up ? acc[a + s] : acc[a]) + recv;
        }
    }
    return acc[0];
}

extern __shared__ float smem[];

__global__ __launch_bounds__(256, 1) void jordan_scan(
    const float* __restrict__ last_logits,
    const float* __restrict__ W_y, const float* __restrict__ b_y,
    const float* __restrict__ W_out, const float* __restrict__ b_out,
    float* __restrict__ out_h, float* __restrict__ out_y,
    float* __restrict__ out_ylast) {
    float* sWy  = smem;                  // 16*512
    float* sWo  = smem + RPB * 512;      // 16*512
    float* sAct = smem + 2 * RPB * 512;  // 16*512

    const int tid = threadIdx.x;
    const int bid = blockIdx.x;
    const int rg = bid & 31;   // row group 0..31
    const int bg = bid >> 5;   // batch group 0..3
    const int r0 = rg * RPB;
    const int b0 = bg * BPB;

    // Preload weight slices (persist all steps)
    for (int q = tid; q < RPB * 512 / 4; q += 256) {
        ((float4*)sWy)[q] = ((const float4*)(W_y + (size_t)r0 * 512))[q];
        ((float4*)sWo)[q] = ((const float4*)(W_out + (size_t)r0 * 512))[q];
    }

    const int w = tid >> 5, kc = tid & 31;
    const int bg2 = w >> 1, rg2 = w & 1;
    const int i2 = kc >> 3, p = kc & 7;
    const int b_out_idx = b0 + bg2 * 4 + i2;   // batch this lane writes
    const int r_out_idx = r0 + rg2 * 8 + p;    // row this lane writes
    const float by_v = b_y[r_out_idx];
    const float bo_v = b_out[r_out_idx];

    const int sb = tid >> 4;   // staging batch 0..15
    const int sc = tid & 15;   // staging quad

    __syncthreads();

    for (int t = 0; t < Tdim; t++) {
        // ---- stage y_prev for this block's 16 batches ----
        {
            const float* src = (t == 0)
                ? last_logits + (size_t)(b0 + sb) * Odim
                : out_y + ((size_t)(b0 + sb) * Tdim + (t - 1)) * Odim;
            float4* dst = (float4*)(sAct + sb * 512);
            const float4* s4 = (const float4*)src;
#pragma unroll
            for (int q = 0; q < 8; q++) dst[sc + 16 * q] = s4[sc + 16 * q];
        }
        __syncthreads();

        // ---- GEMM1: h = tanh(xin + y_prev @ W_y^T + b_y) ----
        {
            float v = matvec_tile(sWy, sAct, kc, bg2, rg2);
            v += g_xin[((size_t)b_out_idx * Tdim + t) * Hdim + r_out_idx] + by_v;
            v = tanhf(v);
            out_h[((size_t)b_out_idx * Tdim + t) * Hdim + r_out_idx] = v;
        }
        __threadfence();
        gridbar();

        // ---- stage h for this block's 16 batches ----
        {
            const float* src = out_h + ((size_t)(b0 + sb) * Tdim + t) * Hdim;
            float4* dst = (float4*)(sAct + sb * 512);
            const float4* s4 = (const float4*)src;
#pragma unroll
            for (int q = 0; q < 8; q++) dst[sc + 16 * q] = s4[sc + 16 * q];
        }
        __syncthreads();

        // ---- GEMM2: y = h @ W_out^T + b_out ----
        {
            float v = matvec_tile(sWo, sAct, kc, bg2, rg2);
            v += bo_v;
            out_y[((size_t)b_out_idx * Tdim + t) * Odim + r_out_idx] = v;
            if (t == Tdim - 1) out_ylast[(size_t)b_out_idx * Odim + r_out_idx] = v;
        }
        __threadfence();
        gridbar();
    }
}

// ---------------------------------------------------------------------------
extern "C" void kernel_launch(void* const* d_in, const int* in_sizes, int n_in,
                              void* d_out, int out_size) {
    const float* emb    = (const float*)d_in[0];
    const float* lastlg = (const float*)d_in[1];
    const float* W_in   = (const float*)d_in[2];
    const float* b_in   = (const float*)d_in[3];
    const float* W_y    = (const float*)d_in[4];
    const float* b_y    = (const float*)d_in[5];
    const float* W_out  = (const float*)d_in[6];
    const float* b_out  = (const float*)d_in[7];

    float* out    = (float*)d_out;
    float* out_h  = out;
    float* out_y  = out + (size_t)Bdim * Tdim * Hdim;
    float* out_yl = out + (size_t)2 * Bdim * Tdim * Hdim;

    const int smem_bytes = 3 * RPB * 512 * sizeof(float);  // 96 KB
    cudaFuncSetAttribute(jordan_scan,
                         cudaFuncAttributeMaxDynamicSharedMemorySize, smem_bytes);

    dim3 gA(Hdim / BN, (Bdim * Tdim) / BM);
    gemm_xin<<<gA, 256>>>(emb, W_in, b_in);

    jordan_scan<<<NBLK, 256, smem_bytes>>>(lastlg, W_y, b_y, W_out, b_out,
                                           out_h, out_y, out_yl);
}